// round 13
// baseline (speedup 1.0000x reference)
#include <cuda_runtime.h>
#include <cuda_bf16.h>

#define Bq 32
#define Nq 325
#define Kq 20
#define S_IN 12
#define S_OUTq 12
#define Cq 10
#define Hq 48            // 4*S_OUT
#define BNq (Bq*Nq)      // 10400
#define K2G (BNq/4)      // 2600 k2 blocks
#define FULLM 0xffffffffu

typedef unsigned long long ull;

__device__ float g_wh[BNq*S_OUTq];
__device__ float g_hx[BNq*Hq];
__device__ float g_hy[BNq*Hq];
__device__ float g_wT[Cq*Hq];    // a2_W transposed (contiguous)
__device__ double g_acc[3] = {0.0, 0.0, 0.0};   // wh_sum, dist_sum, cl_sum
__device__ int g_counter = 0;

__device__ __forceinline__ float leaky(float x){ return x >= 0.f ? x : 0.5f*x; }

// ---- f32x2 packed helpers (sm_103a; FFMA2 via PTX) ----
__device__ __forceinline__ ull pk2(float lo, float hi){
    ull r;
    asm("mov.b64 %0, {%1, %2};" : "=l"(r) : "f"(lo), "f"(hi));
    return r;
}
__device__ __forceinline__ void fma2(ull& d, ull a, ull b){
    asm("fma.rn.f32x2 %0, %1, %2, %0;" : "+l"(d) : "l"(a), "l"(b));
}
__device__ __forceinline__ float2 up2(ull v){
    float a, b;
    asm("mov.b64 {%0, %1}, %2;" : "=f"(a), "=f"(b) : "l"(v));
    return make_float2(a, b);
}

// ---------------- k1: warp per (b,n) row ----------------
__global__ __launch_bounds__(256) void k1(
        const float* __restrict__ inp, const float* __restrict__ wW,
        const float* __restrict__ wb,  const float* __restrict__ a1W,
        const float* __restrict__ a2W){
    int t = threadIdx.x;
    int warp = t >> 5, lane = t & 31;
    int bn = blockIdx.x * 8 + warp;

    if (blockIdx.x == 0) {   // transpose a2_W once
        for (int i = t; i < Cq*Hq; i += 256) {
            int c = i / Hq, d = i % Hq;
            g_wT[c*Hq + d] = a2W[d*Cq + c];
        }
    }

    float whsum = 0.f;
    if (bn < BNq) {
        float xin = (lane < S_IN) ? inp[bn*S_IN + lane] : 0.f;
        float wh = (lane < S_OUTq) ? wb[lane] : 0.f;
        #pragma unroll
        for (int i = 0; i < S_IN; i++) {
            float xi = __shfl_sync(FULLM, xin, i);
            if (lane < S_OUTq) wh += xi * wW[i*S_OUTq + lane];
        }
        wh = leaky(wh);
        if (lane < S_OUTq) { g_wh[bn*S_OUTq + lane] = wh; whsum = wh; }

        int d2 = 32 + (lane & 15);
        float ax = 0.f, ay = 0.f, ax2 = 0.f, ay2 = 0.f;
        #pragma unroll
        for (int s = 0; s < S_OUTq; s++) {
            float w = __shfl_sync(FULLM, wh, s);
            ax  += w * a1W[s*Hq + lane];
            ay  += w * a1W[(S_OUTq+s)*Hq + lane];
            ax2 += w * a1W[s*Hq + d2];
            ay2 += w * a1W[(S_OUTq+s)*Hq + d2];
        }
        g_hx[bn*Hq + lane] = ax;
        g_hy[bn*Hq + lane] = ay;
        if (lane < 16) { g_hx[bn*Hq + d2] = ax2; g_hy[bn*Hq + d2] = ay2; }
    }
    #pragma unroll
    for (int o = 16; o; o >>= 1) whsum += __shfl_down_sync(FULLM, whsum, o);
    __shared__ float sred[8];
    if (lane == 0) sred[warp] = whsum;
    __syncthreads();
    if (t == 0) {
        float s = 0.f;
        #pragma unroll
        for (int w = 0; w < 8; w++) s += sred[w];
        atomicAdd(&g_acc[0], (double)s);
    }
}

// ---------------- k2: warp per (b,n); packed pairs, minimal MIO ----------------
__global__ __launch_bounds__(128) void k2(
        const float* __restrict__ a1b, const float* __restrict__ a2b,
        const int* __restrict__ idx, float* __restrict__ out, int out_size){
    int t = threadIdx.x;
    int warp = t >> 5, lane = t & 31;
    int bn = blockIdx.x * 4 + warp;
    int b  = bn / Nq;

    __shared__ __align__(16) float s_wT[Cq*Hq];
    __shared__ __align__(16) float s_hxb[4][Hq];
    __shared__ __align__(16) float s_wht[4][Kq][12];    // row-major (einsum)
    __shared__ __align__(16) float s_attR[4][Cq][Kq];   // c-major (einsum)
    __shared__ ull s_wtn2[4][6][Kq];                    // packed transposed wtn (pairs)
    __shared__ ull s_att2[4][5][Kq];                    // packed transposed att (pairs)
    __shared__ float s_a2b[Cq];
    __shared__ float s_rd[4], s_rc[4];

    for (int i = t; i < 120; i += 128)
        ((float4*)s_wT)[i] = ((const float4*)g_wT)[i];
    if (t < Cq) s_a2b[t] = a2b[t];

    if (lane < 12) {
        float4 hx = ((const float4*)(g_hx + (size_t)bn*Hq))[lane];
        float4 bb = ((const float4*)a1b)[lane];
        ((float4*)s_hxb[warp])[lane] =
            make_float4(hx.x+bb.x, hx.y+bb.y, hx.z+bb.z, hx.w+bb.w);
    }
    int j = 0;
    if (lane < Kq) {
        j = idx[bn*Kq + lane];
        const float4* wp = (const float4*)(g_wh + (size_t)(b*Nq + j)*S_OUTq);
        float4 w0 = wp[0], w1 = wp[1], w2 = wp[2];
        ((float4*)s_wht[warp][lane])[0] = w0;
        ((float4*)s_wht[warp][lane])[1] = w1;
        ((float4*)s_wht[warp][lane])[2] = w2;
        float ss = w0.x*w0.x + w0.y*w0.y + w0.z*w0.z + w0.w*w0.w
                 + w1.x*w1.x + w1.y*w1.y + w1.z*w1.z + w1.w*w1.w
                 + w2.x*w2.x + w2.y*w2.y + w2.z*w2.z + w2.w*w2.w;
        float inv = __fdividef(1.f, sqrtf(ss) + 1e-8f);
        // pre-normalized rows, packed transposed (matches reference wtn exactly)
        s_wtn2[warp][0][lane] = pk2(w0.x*inv, w0.y*inv);
        s_wtn2[warp][1][lane] = pk2(w0.z*inv, w0.w*inv);
        s_wtn2[warp][2][lane] = pk2(w1.x*inv, w1.y*inv);
        s_wtn2[warp][3][lane] = pk2(w1.z*inv, w1.w*inv);
        s_wtn2[warp][4][lane] = pk2(w2.x*inv, w2.y*inv);
        s_wtn2[warp][5][lane] = pk2(w2.z*inv, w2.w*inv);
    }
    __syncthreads();

    // GEMM row k=lane: f32x2, wT consumed as ulonglong2 (no pack movs)
    float att[Cq];
    if (lane < Kq) {
        const float4* hy = (const float4*)(g_hy + (size_t)(b*Nq + j)*Hq);
        ull pacc[Cq];
        #pragma unroll
        for (int c = 0; c < Cq; c++) pacc[c] = pk2(s_a2b[c], 0.f);
        #pragma unroll 4
        for (int q = 0; q < 12; q++) {
            float4 h = hy[q];
            float4 x = ((const float4*)s_hxb[warp])[q];
            ull hA = pk2(leaky(h.x + x.x), leaky(h.y + x.y));
            ull hB = pk2(leaky(h.z + x.z), leaky(h.w + x.w));
            #pragma unroll
            for (int c = 0; c < Cq; c++) {
                ulonglong2 wv = ((const ulonglong2*)(s_wT + c*Hq))[q];  // broadcast
                fma2(pacc[c], hA, wv.x);
                fma2(pacc[c], hB, wv.y);
            }
        }
        float m = -1e30f;
        #pragma unroll
        for (int c = 0; c < Cq; c++) {
            float2 u = up2(pacc[c]);
            att[c] = leaky(u.x + u.y);
            m = fmaxf(m, att[c]);
        }
        float sum = 0.f;
        #pragma unroll
        for (int c = 0; c < Cq; c++) { att[c] = __expf(att[c] - m); sum += att[c]; }
        float inv = __fdividef(1.f, sum);
        #pragma unroll
        for (int c = 0; c < Cq; c++) att[c] *= inv;
        #pragma unroll
        for (int c2 = 0; c2 < 5; c2++)
            s_att2[warp][c2][lane] = pk2(att[2*c2], att[2*c2+1]);
        #pragma unroll
        for (int c = 0; c < Cq; c++) s_attR[warp][c][lane] = att[c];
    }
    __syncwarp();

    // pairs: rotation, packed LDS.64 reads, own rows in packed regs
    float dsum = 0.f, csum = 0.f;
    if (lane < Kq) {
        ull mwtn[6], matt[5];
        #pragma unroll
        for (int i2 = 0; i2 < 6; i2++) mwtn[i2] = s_wtn2[warp][i2][lane];
        #pragma unroll
        for (int c2 = 0; c2 < 5; c2++) matt[c2] = pk2(att[2*c2], att[2*c2+1]);
        {   // diagonal = dot(wtn, wtn)
            ull dd = 0ull;
            #pragma unroll
            for (int i2 = 0; i2 < 6; i2++) fma2(dd, mwtn[i2], mwtn[i2]);
            float2 u = up2(dd);
            dsum = u.x + u.y;
        }
        #pragma unroll 2
        for (int s = 1; s <= 10; s++) {
            int l = lane + s; if (l >= Kq) l -= Kq;
            ull da = 0ull, pa = 0ull;
            #pragma unroll
            for (int i2 = 0; i2 < 6; i2++) fma2(da, mwtn[i2], s_wtn2[warp][i2][l]);
            #pragma unroll
            for (int c2 = 0; c2 < 5; c2++) fma2(pa, matt[c2], s_att2[warp][c2][l]);
            float2 ud = up2(da); float d  = ud.x + ud.y;
            float2 up = up2(pa); float pr = up.x + up.y;
            pr = fminf(fmaxf(pr, 1e-4f), 1.f - 1e-4f);
            float lp = __logf(pr);
            float wgt = (s == 10) ? 1.f : 2.f;
            dsum += wgt * d;
            csum += (d >= 0.5f) ? -wgt*lp : wgt*lp;
        }
    }
    #pragma unroll
    for (int o = 16; o; o >>= 1) {
        dsum += __shfl_down_sync(FULLM, dsum, o);
        csum += __shfl_down_sync(FULLM, csum, o);
    }
    if (lane == 0) { s_rd[warp] = dsum; s_rc[warp] = csum; }

    // einsum: 30 lanes (c,q); att row preloaded to regs (5 LDS.128), wht as ull2
    if (lane < 30) {
        int c = lane / 3, q = lane % 3;
        float areg[Kq];
        #pragma unroll
        for (int i = 0; i < 5; i++)
            ((float4*)areg)[i] = ((const float4*)s_attR[warp][c])[i];
        ull po0 = 0ull, po1 = 0ull;
        #pragma unroll
        for (int k = 0; k < Kq; k++) {
            ull aa = pk2(areg[k], areg[k]);
            ulonglong2 wv = ((const ulonglong2*)s_wht[warp][k])[q];
            fma2(po0, aa, wv.x);
            fma2(po1, aa, wv.y);
        }
        float2 u0 = up2(po0), u1 = up2(po1);
        ((float4*)(out + (size_t)bn*Cq*S_OUTq))[lane] =
            make_float4(u0.x, u0.y, u1.x, u1.y);
    }

    __syncthreads();
    if (t == 0) {
        atomicAdd(&g_acc[1], (double)(s_rd[0] + s_rd[1] + s_rd[2] + s_rd[3]));
        atomicAdd(&g_acc[2], (double)(s_rc[0] + s_rc[1] + s_rc[2] + s_rc[3]));
        __threadfence();
        int done = atomicAdd(&g_counter, 1);
        if (done == K2G - 1) {   // last block finalizes + resets for next replay
            out[out_size - 3] = (float)(g_acc[2] / (double)BNq);
            out[out_size - 2] = (float)(g_acc[1] / (double)((long long)BNq*Kq*Kq));
            out[out_size - 1] = (float)(g_acc[0] / (double)((long long)BNq*S_OUTq));
            g_acc[0] = 0.0; g_acc[1] = 0.0; g_acc[2] = 0.0;
            g_counter = 0;
        }
    }
}

extern "C" void kernel_launch(void* const* d_in, const int* in_sizes, int n_in,
                              void* d_out, int out_size) {
    const float* input_data = (const float*)d_in[1];
    const float* wW  = (const float*)d_in[2];
    const float* wb  = (const float*)d_in[3];
    const float* a1W = (const float*)d_in[4];
    const float* a1b = (const float*)d_in[5];
    const float* a2W = (const float*)d_in[6];
    const float* a2b = (const float*)d_in[7];
    const int*   idx = (const int*)d_in[8];
    float* out = (float*)d_out;

    k1<<<(BNq + 7) / 8, 256>>>(input_data, wW, wb, a1W, a2W);
    k2<<<K2G, 128>>>(a1b, a2b, idx, out, out_size);
}

// round 14
// speedup vs baseline: 1.0894x; 1.0894x over previous
#include <cuda_runtime.h>
#include <cuda_bf16.h>

#define Bq 32
#define Nq 325
#define Kq 20
#define S_IN 12
#define S_OUTq 12
#define Cq 10
#define Hq 48            // 4*S_OUT
#define BNq (Bq*Nq)      // 10400
#define K2G (BNq/4)      // 2600 k2 blocks
#define FULLM 0xffffffffu
#define PADF4 13         // s_hid row stride in float4 (52 floats, odd -> low conflict)

__device__ float g_wh[BNq*S_OUTq];
__device__ float g_hx[BNq*Hq];
__device__ float g_hy[BNq*Hq];
__device__ float g_wT[Cq*Hq];    // a2_W transposed (contiguous)
__device__ double g_acc[3] = {0.0, 0.0, 0.0};   // wh_sum, dist_sum, cl_sum
__device__ int g_counter = 0;

__device__ __forceinline__ float leaky(float x){ return x >= 0.f ? x : 0.5f*x; }

// ---------------- k1: warp per (b,n) row ----------------
__global__ __launch_bounds__(256) void k1(
        const float* __restrict__ inp, const float* __restrict__ wW,
        const float* __restrict__ wb,  const float* __restrict__ a1W,
        const float* __restrict__ a2W){
    int t = threadIdx.x;
    int warp = t >> 5, lane = t & 31;
    int bn = blockIdx.x * 8 + warp;

    if (blockIdx.x == 0) {   // transpose a2_W once
        for (int i = t; i < Cq*Hq; i += 256) {
            int c = i / Hq, d = i % Hq;
            g_wT[c*Hq + d] = a2W[d*Cq + c];
        }
    }

    float whsum = 0.f;
    if (bn < BNq) {
        float xin = (lane < S_IN) ? inp[bn*S_IN + lane] : 0.f;
        float wh = (lane < S_OUTq) ? wb[lane] : 0.f;
        #pragma unroll
        for (int i = 0; i < S_IN; i++) {
            float xi = __shfl_sync(FULLM, xin, i);
            if (lane < S_OUTq) wh += xi * wW[i*S_OUTq + lane];
        }
        wh = leaky(wh);
        if (lane < S_OUTq) { g_wh[bn*S_OUTq + lane] = wh; whsum = wh; }

        int d2 = 32 + (lane & 15);
        float ax = 0.f, ay = 0.f, ax2 = 0.f, ay2 = 0.f;
        #pragma unroll
        for (int s = 0; s < S_OUTq; s++) {
            float w = __shfl_sync(FULLM, wh, s);
            ax  += w * a1W[s*Hq + lane];
            ay  += w * a1W[(S_OUTq+s)*Hq + lane];
            ax2 += w * a1W[s*Hq + d2];
            ay2 += w * a1W[(S_OUTq+s)*Hq + d2];
        }
        g_hx[bn*Hq + lane] = ax;
        g_hy[bn*Hq + lane] = ay;
        if (lane < 16) { g_hx[bn*Hq + d2] = ax2; g_hy[bn*Hq + d2] = ay2; }
    }
    #pragma unroll
    for (int o = 16; o; o >>= 1) whsum += __shfl_down_sync(FULLM, whsum, o);
    __shared__ float sred[8];
    if (lane == 0) sred[warp] = whsum;
    __syncthreads();
    if (t == 0) {
        float s = 0.f;
        #pragma unroll
        for (int w = 0; w < 8; w++) s += sred[w];
        atomicAdd(&g_acc[0], (double)s);
    }
}

// ---------------- k2: warp per (b,n); cooperative hid staging; SHFL pairs ----------------
__global__ __launch_bounds__(128) void k2(
        const float* __restrict__ a1b, const float* __restrict__ a2b,
        const int* __restrict__ idx, float* __restrict__ out, int out_size){
    int t = threadIdx.x;
    int warp = t >> 5, lane = t & 31;
    int bn = blockIdx.x * 4 + warp;
    int b  = bn / Nq;

    __shared__ __align__(16) float s_wT[Cq*Hq];
    __shared__ __align__(16) float s_hxb[4][Hq];
    __shared__ __align__(16) float s_hid[4][Kq][PADF4*4];  // pre-activated hidden rows
    __shared__ __align__(16) float s_att[4][Kq][12];
    __shared__ __align__(16) float s_wht[4][Kq][12];
    __shared__ int   s_j[4][Kq];
    __shared__ float s_a2b[Cq];
    __shared__ float s_rd[4], s_rc[4];

    for (int i = t; i < 120; i += 128)
        ((float4*)s_wT)[i] = ((const float4*)g_wT)[i];
    if (t < Cq) s_a2b[t] = a2b[t];

    if (lane < 12) {
        float4 hx = ((const float4*)(g_hx + (size_t)bn*Hq))[lane];
        float4 bb = ((const float4*)a1b)[lane];
        ((float4*)s_hxb[warp])[lane] =
            make_float4(hx.x+bb.x, hx.y+bb.y, hx.z+bb.z, hx.w+bb.w);
    }
    float w[S_OUTq];               // own wht row in regs
    float myinv = 0.f, myss = 0.f;
    #pragma unroll
    for (int i = 0; i < S_OUTq; i++) w[i] = 0.f;
    if (lane < Kq) {
        int j = idx[bn*Kq + lane];
        s_j[warp][lane] = j;
        const float4* wp = (const float4*)(g_wh + (size_t)(b*Nq + j)*S_OUTq);
        float4 w0 = wp[0], w1 = wp[1], w2 = wp[2];
        ((float4*)s_wht[warp][lane])[0] = w0;
        ((float4*)s_wht[warp][lane])[1] = w1;
        ((float4*)s_wht[warp][lane])[2] = w2;
        w[0]=w0.x; w[1]=w0.y; w[2]=w0.z; w[3]=w0.w;
        w[4]=w1.x; w[5]=w1.y; w[6]=w1.z; w[7]=w1.w;
        w[8]=w2.x; w[9]=w2.y; w[10]=w2.z; w[11]=w2.w;
        #pragma unroll
        for (int i = 0; i < S_OUTq; i++) myss += w[i]*w[i];
        myinv = __fdividef(1.f, sqrtf(myss) + 1e-8f);
    }
    __syncwarp();

    // cooperative staging: 240 float4 items over 32 lanes (8 iters).
    // Fuses bias+leaky; LDG lanes span consecutive q within ~3 rows -> few lines.
    #pragma unroll
    for (int it = 0; it < 8; it++) {
        int i = it*32 + lane;
        if (i < Kq*12) {
            int r = i / 12, q = i - r*12;
            int jr = s_j[warp][r];
            float4 h = ((const float4*)(g_hy + (size_t)(b*Nq + jr)*Hq))[q];
            float4 x = ((const float4*)s_hxb[warp])[q];
            ((float4*)s_hid[warp][r])[q] =
                make_float4(leaky(h.x+x.x), leaky(h.y+x.y),
                            leaky(h.z+x.z), leaky(h.w+x.w));
        }
    }
    __syncwarp();

    // attention row k=lane: hid from smem (own row), wT broadcasts, reg softmax
    float att[Cq];
    #pragma unroll
    for (int c = 0; c < Cq; c++) att[c] = 0.f;
    if (lane < Kq) {
        float acc[Cq];
        #pragma unroll
        for (int c = 0; c < Cq; c++) acc[c] = s_a2b[c];
        #pragma unroll 4
        for (int q = 0; q < 12; q++) {
            float4 h = ((const float4*)s_hid[warp][lane])[q];
            #pragma unroll
            for (int c = 0; c < Cq; c++) {
                float4 wv = ((const float4*)(s_wT + c*Hq))[q];   // broadcast
                acc[c] += h.x*wv.x + h.y*wv.y + h.z*wv.z + h.w*wv.w;
            }
        }
        float m = -1e30f;
        #pragma unroll
        for (int c = 0; c < Cq; c++) { acc[c] = leaky(acc[c]); m = fmaxf(m, acc[c]); }
        float sum = 0.f;
        #pragma unroll
        for (int c = 0; c < Cq; c++) { acc[c] = __expf(acc[c] - m); sum += acc[c]; }
        float inv = __fdividef(1.f, sum);
        #pragma unroll
        for (int c = 0; c < Cq; c++) att[c] = acc[c] * inv;
        ((float4*)s_att[warp][lane])[0] = make_float4(att[0], att[1], att[2], att[3]);
        ((float4*)s_att[warp][lane])[1] = make_float4(att[4], att[5], att[6], att[7]);
        ((float4*)s_att[warp][lane])[2] = make_float4(att[8], att[9], 0.f, 0.f);
    }
    __syncwarp();

    // pairs via incremental register rotation (SHFL; R11 proven-best)
    float dsum = (lane < Kq) ? myss * myinv * myinv : 0.f;   // diagonal
    float csum = 0.f;
    {
        int src = lane + 1; if (src >= Kq) src -= Kq;   // rotation source
        float rw[S_OUTq], ra[Cq], rinv = myinv;
        #pragma unroll
        for (int i = 0; i < S_OUTq; i++) rw[i] = w[i];
        #pragma unroll
        for (int i = 0; i < Cq; i++) ra[i] = att[i];
        #pragma unroll
        for (int s = 1; s <= 10; s++) {
            #pragma unroll
            for (int i = 0; i < S_OUTq; i++) rw[i] = __shfl_sync(FULLM, rw[i], src);
            #pragma unroll
            for (int i = 0; i < Cq; i++) ra[i] = __shfl_sync(FULLM, ra[i], src);
            rinv = __shfl_sync(FULLM, rinv, src);
            if (lane < Kq) {
                float d = 0.f;
                #pragma unroll
                for (int i = 0; i < S_OUTq; i++) d += w[i]*rw[i];
                d *= myinv * rinv;
                float pr = 0.f;
                #pragma unroll
                for (int i = 0; i < Cq; i++) pr += att[i]*ra[i];
                pr = fminf(fmaxf(pr, 1e-4f), 1.f - 1e-4f);
                float lp = __logf(pr);
                float wgt = (s == 10) ? 1.f : 2.f;
                dsum += wgt * d;
                csum += (d >= 0.5f) ? -wgt*lp : wgt*lp;
            }
        }
    }
    #pragma unroll
    for (int o = 16; o; o >>= 1) {
        dsum += __shfl_down_sync(FULLM, dsum, o);
        csum += __shfl_down_sync(FULLM, csum, o);
    }
    if (lane == 0) { s_rd[warp] = dsum; s_rc[warp] = csum; }

    // einsum: 30 lanes, 30 float4 outputs
    if (lane < 30) {
        int c = lane / 3, q = lane % 3;
        float4 o = make_float4(0.f, 0.f, 0.f, 0.f);
        #pragma unroll
        for (int k = 0; k < Kq; k++) {
            float a = s_att[warp][k][c];
            float4 wv = ((const float4*)s_wht[warp][k])[q];
            o.x += a*wv.x; o.y += a*wv.y; o.z += a*wv.z; o.w += a*wv.w;
        }
        ((float4*)(out + (size_t)bn*Cq*S_OUTq))[lane] = o;
    }

    __syncthreads();
    if (t == 0) {
        atomicAdd(&g_acc[1], (double)(s_rd[0] + s_rd[1] + s_rd[2] + s_rd[3]));
        atomicAdd(&g_acc[2], (double)(s_rc[0] + s_rc[1] + s_rc[2] + s_rc[3]));
        __threadfence();
        int done = atomicAdd(&g_counter, 1);
        if (done == K2G - 1) {   // last block finalizes + resets for next replay
            out[out_size - 3] = (float)(g_acc[2] / (double)BNq);
            out[out_size - 2] = (float)(g_acc[1] / (double)((long long)BNq*Kq*Kq));
            out[out_size - 1] = (float)(g_acc[0] / (double)((long long)BNq*S_OUTq));
            g_acc[0] = 0.0; g_acc[1] = 0.0; g_acc[2] = 0.0;
            g_counter = 0;
        }
    }
}

extern "C" void kernel_launch(void* const* d_in, const int* in_sizes, int n_in,
                              void* d_out, int out_size) {
    const float* input_data = (const float*)d_in[1];
    const float* wW  = (const float*)d_in[2];
    const float* wb  = (const float*)d_in[3];
    const float* a1W = (const float*)d_in[4];
    const float* a1b = (const float*)d_in[5];
    const float* a2W = (const float*)d_in[6];
    const float* a2b = (const float*)d_in[7];
    const int*   idx = (const int*)d_in[8];
    float* out = (float*)d_out;

    k1<<<(BNq + 7) / 8, 256>>>(input_data, wW, wb, a1W, a2W);
    k2<<<K2G, 128>>>(a1b, a2b, idx, out, out_size);
}